// round 1
// baseline (speedup 1.0000x reference)
#include <cuda_runtime.h>

#define N_NODES 50000
#define N_EDGES 800000
#define HID 128

// Persistent scratch (allocation-free rule: __device__ globals)
__device__ float g_agg[(size_t)N_NODES * HID];
__device__ float g_h[(size_t)N_NODES * HID];
__device__ int g_is64;

// ---------------------------------------------------------------------------
// Detect whether edge_index is int64 or int32 (JAX without x64 demotes to i32)
// ---------------------------------------------------------------------------
__global__ void detect_kernel(const long long* __restrict__ ei) {
    if (threadIdx.x == 0 && blockIdx.x == 0) {
        int ok = 1;
        for (int i = 0; i < 64; i++) {
            long long v = ei[i];
            if (v < 0 || v >= N_NODES) { ok = 0; break; }
        }
        g_is64 = ok;
    }
}

// ---------------------------------------------------------------------------
// Zero the aggregation buffer
// ---------------------------------------------------------------------------
__global__ void zero_kernel() {
    size_t i = (size_t)blockIdx.x * blockDim.x + threadIdx.x;
    float4* a = (float4*)g_agg;
    const size_t total = (size_t)N_NODES * (HID / 4);
    const size_t stride = (size_t)gridDim.x * blockDim.x;
    for (; i < total; i += stride) a[i] = make_float4(0.f, 0.f, 0.f, 0.f);
}

// ---------------------------------------------------------------------------
// Scatter-add: one warp per edge, 128 floats = 32 lanes x float4.
// Uses vectorized red.global.add.v4.f32 (sm_90+).
// ---------------------------------------------------------------------------
__global__ void scatter_kernel(const float* __restrict__ x, int use_gh,
                               const void* __restrict__ ei) {
    const float* h = use_gh ? g_h : x;
    const int lane = threadIdx.x & 31;
    size_t w = ((size_t)blockIdx.x * blockDim.x + threadIdx.x) >> 5;
    const size_t nw = ((size_t)gridDim.x * blockDim.x) >> 5;
    const int is64 = g_is64;
    const long long* e64 = (const long long*)ei;
    const int* e32 = (const int*)ei;
    for (size_t e = w; e < (size_t)N_EDGES; e += nw) {
        long long src, dst;
        if (is64) { src = e64[e]; dst = e64[N_EDGES + e]; }
        else      { src = e32[e]; dst = e32[N_EDGES + e]; }
        float4 v = __ldg((const float4*)(h + (size_t)src * HID) + lane);
        float* p = g_agg + (size_t)dst * HID + lane * 4;
        asm volatile("red.global.add.v4.f32 [%0], {%1,%2,%3,%4};"
                     :: "l"(p), "f"(v.x), "f"(v.y), "f"(v.z), "f"(v.w)
                     : "memory");
    }
}

// ---------------------------------------------------------------------------
// Fused GIN MLP for one layer:
//   z = (1+eps[l])*h + agg          (fused into load)
//   t = relu(z @ Wa + ba)
//   h_out = relu(t @ Wb + bb)       (written to g_h, in-place safe per-block)
// Block: 128 rows, 256 threads, 8x8 register tile per thread.
// smem: zs[128][132] + ws[128][128] = 133,120 bytes (dynamic).
// ---------------------------------------------------------------------------
#define MLP_SMEM (size_t)((128 * 132 + 128 * 128) * sizeof(float))

__global__ __launch_bounds__(256) void mlp_kernel(
    const float* __restrict__ x, int use_gh,
    const float* __restrict__ eps, int l,
    const float* __restrict__ Wa, const float* __restrict__ ba,
    const float* __restrict__ Wb, const float* __restrict__ bb) {
    extern __shared__ float sm[];
    float* zs = sm;               // 128 x 132 (padded)
    float* ws = sm + 128 * 132;   // 128 x 128

    const float* h = use_gh ? g_h : x;
    const int tid = threadIdx.x;
    const int tx = tid & 15, ty = tid >> 4;
    const int row0 = blockIdx.x * 128;
    const float s = 1.0f + eps[l];

    const float4* h4 = (const float4*)h;
    const float4* a4 = (const float4*)g_agg;

    // Load z block = (1+eps)*h + agg (zero-fill OOB rows)
    for (int i = tid; i < 128 * 32; i += 256) {
        int r = i >> 5, c = i & 31;
        int gr = row0 + r;
        float4 v = make_float4(0.f, 0.f, 0.f, 0.f);
        if (gr < N_NODES) {
            size_t idx = (size_t)gr * 32 + c;
            float4 hv = h4[idx];
            float4 av = a4[idx];
            v.x = fmaf(s, hv.x, av.x);
            v.y = fmaf(s, hv.y, av.y);
            v.z = fmaf(s, hv.z, av.z);
            v.w = fmaf(s, hv.w, av.w);
        }
        *(float4*)&zs[r * 132 + c * 4] = v;
    }
    // Load Wa
    const float4* wa4 = (const float4*)Wa;
    for (int i = tid; i < 128 * 32; i += 256)
        *(float4*)&ws[(i >> 5) * 128 + (i & 31) * 4] = wa4[i];
    __syncthreads();

    float acc[8][8];
#pragma unroll
    for (int i = 0; i < 8; i++)
#pragma unroll
        for (int j = 0; j < 8; j++) acc[i][j] = 0.f;

    // Stage 1: z @ Wa
#pragma unroll 4
    for (int k = 0; k < 128; k++) {
        float b[8];
        *(float4*)&b[0] = *(const float4*)&ws[k * 128 + tx * 8];
        *(float4*)&b[4] = *(const float4*)&ws[k * 128 + tx * 8 + 4];
#pragma unroll
        for (int i = 0; i < 8; i++) {
            float a = zs[(ty * 8 + i) * 132 + k];
#pragma unroll
            for (int j = 0; j < 8; j++) acc[i][j] = fmaf(a, b[j], acc[i][j]);
        }
    }
    float bi[8];
    *(float4*)&bi[0] = *(const float4*)&ba[tx * 8];
    *(float4*)&bi[4] = *(const float4*)&ba[tx * 8 + 4];
    __syncthreads();

    // Write t = relu(acc + ba) back into zs; load Wb into ws
#pragma unroll
    for (int i = 0; i < 8; i++) {
        float t[8];
#pragma unroll
        for (int j = 0; j < 8; j++) t[j] = fmaxf(acc[i][j] + bi[j], 0.f);
        *(float4*)&zs[(ty * 8 + i) * 132 + tx * 8] = *(float4*)&t[0];
        *(float4*)&zs[(ty * 8 + i) * 132 + tx * 8 + 4] = *(float4*)&t[4];
    }
    const float4* wb4 = (const float4*)Wb;
    for (int i = tid; i < 128 * 32; i += 256)
        *(float4*)&ws[(i >> 5) * 128 + (i & 31) * 4] = wb4[i];
    __syncthreads();

#pragma unroll
    for (int i = 0; i < 8; i++)
#pragma unroll
        for (int j = 0; j < 8; j++) acc[i][j] = 0.f;

    // Stage 2: t @ Wb
#pragma unroll 4
    for (int k = 0; k < 128; k++) {
        float b[8];
        *(float4*)&b[0] = *(const float4*)&ws[k * 128 + tx * 8];
        *(float4*)&b[4] = *(const float4*)&ws[k * 128 + tx * 8 + 4];
#pragma unroll
        for (int i = 0; i < 8; i++) {
            float a = zs[(ty * 8 + i) * 132 + k];
#pragma unroll
            for (int j = 0; j < 8; j++) acc[i][j] = fmaf(a, b[j], acc[i][j]);
        }
    }
    *(float4*)&bi[0] = *(const float4*)&bb[tx * 8];
    *(float4*)&bi[4] = *(const float4*)&bb[tx * 8 + 4];

    // h_out = relu(acc + bb) -> g_h
#pragma unroll
    for (int i = 0; i < 8; i++) {
        int gr = row0 + ty * 8 + i;
        if (gr < N_NODES) {
            float t[8];
#pragma unroll
            for (int j = 0; j < 8; j++) t[j] = fmaxf(acc[i][j] + bi[j], 0.f);
            float* o = g_h + (size_t)gr * 128 + tx * 8;
            *(float4*)&o[0] = *(float4*)&t[0];
            *(float4*)&o[4] = *(float4*)&t[4];
        }
    }
}

// ---------------------------------------------------------------------------
// Head: out = relu(h @ W1 + b1) @ W2 + b2    (128 -> 64 -> 2)
// Block: 64 rows, 256 threads, 4x4 register tile for stage 1.
// ---------------------------------------------------------------------------
#define HEAD_SMEM (size_t)((64 * 132 + 128 * 64 + 64 * 68) * sizeof(float))

__global__ __launch_bounds__(256) void head_kernel(
    const float* __restrict__ W1, const float* __restrict__ b1,
    const float* __restrict__ W2, const float* __restrict__ b2,
    float* __restrict__ out) {
    extern __shared__ float sm[];
    float* hs = sm;                 // 64 x 132
    float* w1 = sm + 64 * 132;      // 128 x 64
    float* hid = w1 + 128 * 64;     // 64 x 68

    const int tid = threadIdx.x;
    const int tx = tid & 15, ty = tid >> 4;
    const int row0 = blockIdx.x * 64;

    const float4* h4 = (const float4*)g_h;
    for (int i = tid; i < 64 * 32; i += 256) {
        int r = i >> 5, c = i & 31;
        int gr = row0 + r;
        float4 v = make_float4(0.f, 0.f, 0.f, 0.f);
        if (gr < N_NODES) v = h4[(size_t)gr * 32 + c];
        *(float4*)&hs[r * 132 + c * 4] = v;
    }
    const float4* w14 = (const float4*)W1;
    for (int i = tid; i < 128 * 16; i += 256)
        *(float4*)&w1[(i >> 4) * 64 + (i & 15) * 4] = w14[i];
    __syncthreads();

    float acc[4][4];
#pragma unroll
    for (int i = 0; i < 4; i++)
#pragma unroll
        for (int j = 0; j < 4; j++) acc[i][j] = 0.f;

#pragma unroll 4
    for (int k = 0; k < 128; k++) {
        float b[4];
        *(float4*)&b[0] = *(const float4*)&w1[k * 64 + tx * 4];
#pragma unroll
        for (int i = 0; i < 4; i++) {
            float a = hs[(ty * 4 + i) * 132 + k];
#pragma unroll
            for (int j = 0; j < 4; j++) acc[i][j] = fmaf(a, b[j], acc[i][j]);
        }
    }
    float bi[4];
    *(float4*)&bi[0] = *(const float4*)&b1[tx * 4];
#pragma unroll
    for (int i = 0; i < 4; i++) {
        float t[4];
#pragma unroll
        for (int j = 0; j < 4; j++) t[j] = fmaxf(acc[i][j] + bi[j], 0.f);
        *(float4*)&hid[(ty * 4 + i) * 68 + tx * 4] = *(float4*)&t[0];
    }
    __syncthreads();

    if (tid < 128) {
        int r = tid >> 1, c = tid & 1;
        int gr = row0 + r;
        if (gr < N_NODES) {
            float s = __ldg(&b2[c]);
#pragma unroll 8
            for (int k = 0; k < 64; k++)
                s = fmaf(hid[r * 68 + k], __ldg(&W2[k * 2 + c]), s);
            out[(size_t)gr * 2 + c] = s;
        }
    }
}

// ---------------------------------------------------------------------------
extern "C" void kernel_launch(void* const* d_in, const int* in_sizes, int n_in,
                              void* d_out, int out_size) {
    const float* x   = (const float*)d_in[0];
    const void*  ei  = d_in[1];
    const float* eps = (const float*)d_in[2];
    const float* Wa  = (const float*)d_in[3];
    const float* ba  = (const float*)d_in[4];
    const float* Wb  = (const float*)d_in[5];
    const float* bb  = (const float*)d_in[6];
    const float* W1  = (const float*)d_in[7];
    const float* b1  = (const float*)d_in[8];
    const float* W2  = (const float*)d_in[9];
    const float* b2  = (const float*)d_in[10];
    float* out = (float*)d_out;

    cudaFuncSetAttribute(mlp_kernel, cudaFuncAttributeMaxDynamicSharedMemorySize,
                         (int)MLP_SMEM);
    cudaFuncSetAttribute(head_kernel, cudaFuncAttributeMaxDynamicSharedMemorySize,
                         (int)HEAD_SMEM);

    detect_kernel<<<1, 32>>>((const long long*)ei);

    const int mlp_blocks = (N_NODES + 127) / 128;   // 391
    const int head_blocks = (N_NODES + 63) / 64;    // 782

    for (int l = 0; l < 3; l++) {
        zero_kernel<<<1024, 256>>>();
        scatter_kernel<<<2048, 256>>>(x, l > 0 ? 1 : 0, ei);
        mlp_kernel<<<mlp_blocks, 256, MLP_SMEM>>>(
            x, l > 0 ? 1 : 0, eps, l,
            Wa + (size_t)l * HID * HID, ba + (size_t)l * HID,
            Wb + (size_t)l * HID * HID, bb + (size_t)l * HID);
    }
    head_kernel<<<head_blocks, 256, HEAD_SMEM>>>(W1, b1, W2, b2, out);
}

// round 2
// speedup vs baseline: 1.0776x; 1.0776x over previous
#include <cuda_runtime.h>

#define N_NODES 50000
#define N_EDGES 800000
#define HID 128

// Persistent scratch (allocation-free rule: __device__ globals)
__device__ float g_agg[(size_t)N_NODES * HID];   // holds z = (1+eps)h + agg
__device__ float g_h[(size_t)N_NODES * HID];
__device__ int   g_deg[N_NODES];
__device__ int   g_off[N_NODES + 1];
__device__ int   g_cursor[N_NODES];
__device__ int   g_csr[N_EDGES];
__device__ int   g_is64;

// f32x2 packed-FMA helpers (sm_100+; ptxas never emits these from C++)
#define FMA2(d, a, b) asm("fma.rn.f32x2 %0,%1,%2,%0;" : "+l"(d) : "l"(a), "l"(b))
#define PACK2(d, x, y) asm("mov.b64 %0,{%1,%2};" : "=l"(d) : "f"(x), "f"(y))
#define UNPACK2(x, y, d) asm("mov.b64 {%0,%1},%2;" : "=f"(x), "=f"(y) : "l"(d))

// ---------------------------------------------------------------------------
// Detect whether edge_index is int64 or int32
// ---------------------------------------------------------------------------
__global__ void detect_kernel(const long long* __restrict__ ei) {
    if (threadIdx.x == 0 && blockIdx.x == 0) {
        int ok = 1;
        for (int i = 0; i < 64; i++) {
            long long v = ei[i];
            if (v < 0 || v >= N_NODES) { ok = 0; break; }
        }
        g_is64 = ok;
    }
}

// ---------------------------------------------------------------------------
// CSR build: zero degrees -> histogram -> scan -> cursor copy -> fill
// ---------------------------------------------------------------------------
__global__ void zero_deg_kernel() {
    int i = blockIdx.x * blockDim.x + threadIdx.x;
    if (i < N_NODES) g_deg[i] = 0;
}

__global__ void hist_kernel(const void* __restrict__ ei) {
    const int is64 = g_is64;
    const long long* e64 = (const long long*)ei;
    const int* e32 = (const int*)ei;
    size_t i = (size_t)blockIdx.x * blockDim.x + threadIdx.x;
    const size_t stride = (size_t)gridDim.x * blockDim.x;
    for (size_t e = i; e < (size_t)N_EDGES; e += stride) {
        int dst = is64 ? (int)e64[N_EDGES + e] : e32[N_EDGES + e];
        atomicAdd(&g_deg[dst], 1);
    }
}

__global__ void scan_kernel() {
    __shared__ int sm[1024];
    const int t = threadIdx.x;
    const int CH = (N_NODES + 1023) / 1024;  // 49
    const int base = t * CH;
    int s = 0;
    for (int i = 0; i < CH; i++) {
        int idx = base + i;
        if (idx < N_NODES) s += g_deg[idx];
    }
    sm[t] = s;
    __syncthreads();
    int v = s;
    for (int d = 1; d < 1024; d <<= 1) {
        int o = (t >= d) ? sm[t - d] : 0;
        __syncthreads();
        v += o;
        sm[t] = v;
        __syncthreads();
    }
    int run = v - s;  // exclusive prefix
    for (int i = 0; i < CH; i++) {
        int idx = base + i;
        if (idx < N_NODES) { g_off[idx] = run; run += g_deg[idx]; }
    }
    if (t == 1023) g_off[N_NODES] = v;
}

__global__ void cursor_kernel() {
    int i = blockIdx.x * blockDim.x + threadIdx.x;
    if (i < N_NODES) g_cursor[i] = g_off[i];
}

__global__ void fill_kernel(const void* __restrict__ ei) {
    const int is64 = g_is64;
    const long long* e64 = (const long long*)ei;
    const int* e32 = (const int*)ei;
    size_t i = (size_t)blockIdx.x * blockDim.x + threadIdx.x;
    const size_t stride = (size_t)gridDim.x * blockDim.x;
    for (size_t e = i; e < (size_t)N_EDGES; e += stride) {
        int src, dst;
        if (is64) { src = (int)e64[e]; dst = (int)e64[N_EDGES + e]; }
        else      { src = e32[e];      dst = e32[N_EDGES + e]; }
        int pos = atomicAdd(&g_cursor[dst], 1);
        g_csr[pos] = src;
    }
}

// ---------------------------------------------------------------------------
// Gather (atomic-free): one warp per node.
//   z[node] = (1+eps[l]) * h[node] + sum_{s in N(node)} h[s]   -> g_agg
// ---------------------------------------------------------------------------
__global__ __launch_bounds__(256) void gather_kernel(
    const float* __restrict__ x, int use_gh,
    const float* __restrict__ eps, int l) {
    const float* h = use_gh ? g_h : x;
    const int node = (int)(((size_t)blockIdx.x * blockDim.x + threadIdx.x) >> 5);
    const int lane = threadIdx.x & 31;
    if (node >= N_NODES) return;
    const int s0 = g_off[node], s1 = g_off[node + 1];
    const float4* h4 = (const float4*)h;

    float4 acc = make_float4(0.f, 0.f, 0.f, 0.f);
    float4 acc2 = make_float4(0.f, 0.f, 0.f, 0.f);
    int i = s0;
    for (; i + 1 < s1; i += 2) {
        int sa = __ldg(&g_csr[i]);
        int sb = __ldg(&g_csr[i + 1]);
        float4 va = __ldg(&h4[(size_t)sa * 32 + lane]);
        float4 vb = __ldg(&h4[(size_t)sb * 32 + lane]);
        acc.x += va.x; acc.y += va.y; acc.z += va.z; acc.w += va.w;
        acc2.x += vb.x; acc2.y += vb.y; acc2.z += vb.z; acc2.w += vb.w;
    }
    if (i < s1) {
        int sa = __ldg(&g_csr[i]);
        float4 va = __ldg(&h4[(size_t)sa * 32 + lane]);
        acc.x += va.x; acc.y += va.y; acc.z += va.z; acc.w += va.w;
    }
    acc.x += acc2.x; acc.y += acc2.y; acc.z += acc2.z; acc.w += acc2.w;

    const float sc = 1.0f + eps[l];
    float4 hv = h4[(size_t)node * 32 + lane];
    acc.x = fmaf(sc, hv.x, acc.x);
    acc.y = fmaf(sc, hv.y, acc.y);
    acc.z = fmaf(sc, hv.z, acc.z);
    acc.w = fmaf(sc, hv.w, acc.w);
    *(float4*)&g_agg[(size_t)node * 128 + lane * 4] = acc;
}

// ---------------------------------------------------------------------------
// Fused GIN MLP (packed f32x2 FMAs):
//   t = relu(z @ Wa + ba);  h_out = relu(t @ Wb + bb)  -> g_h
// Block: 128 rows, 256 threads, 8 rows x 8 cols (as 4 f32x2 pairs) per thread.
// ---------------------------------------------------------------------------
#define MLP_SMEM (size_t)((128 * 132 + 128 * 128) * sizeof(float))

__global__ __launch_bounds__(256) void mlp_kernel(
    const float* __restrict__ Wa, const float* __restrict__ ba,
    const float* __restrict__ Wb, const float* __restrict__ bb) {
    extern __shared__ float sm[];
    float* zs = sm;              // 128 x 132 (padded)
    float* ws = sm + 128 * 132;  // 128 x 128

    const int tid = threadIdx.x;
    const int tx = tid & 15, ty = tid >> 4;
    const int row0 = blockIdx.x * 128;

    // Load z tile (zero-fill OOB rows)
    const float4* z4 = (const float4*)g_agg;
    for (int i = tid; i < 128 * 32; i += 256) {
        int r = i >> 5, c = i & 31;
        int gr = row0 + r;
        float4 v = make_float4(0.f, 0.f, 0.f, 0.f);
        if (gr < N_NODES) v = z4[(size_t)gr * 32 + c];
        *(float4*)&zs[r * 132 + c * 4] = v;
    }
    const float4* wa4 = (const float4*)Wa;
    for (int i = tid; i < 128 * 32; i += 256)
        *(float4*)&ws[(i >> 5) * 128 + (i & 31) * 4] = wa4[i];
    __syncthreads();

    unsigned long long acc[8][4];
#pragma unroll
    for (int i = 0; i < 8; i++)
#pragma unroll
        for (int j = 0; j < 4; j++) acc[i][j] = 0ull;

    // Stage 1: z @ Wa  (f32x2: each acc lane holds 2 output columns)
#pragma unroll 2
    for (int k = 0; k < 128; k++) {
        float4 bA = *(const float4*)&ws[k * 128 + tx * 8];
        float4 bB = *(const float4*)&ws[k * 128 + tx * 8 + 4];
        unsigned long long b0, b1, b2, b3;
        PACK2(b0, bA.x, bA.y); PACK2(b1, bA.z, bA.w);
        PACK2(b2, bB.x, bB.y); PACK2(b3, bB.z, bB.w);
#pragma unroll
        for (int i = 0; i < 8; i++) {
            float a = zs[(ty * 8 + i) * 132 + k];
            unsigned long long a2; PACK2(a2, a, a);
            FMA2(acc[i][0], a2, b0); FMA2(acc[i][1], a2, b1);
            FMA2(acc[i][2], a2, b2); FMA2(acc[i][3], a2, b3);
        }
    }
    float bi[8];
    *(float4*)&bi[0] = *(const float4*)&ba[tx * 8];
    *(float4*)&bi[4] = *(const float4*)&ba[tx * 8 + 4];
    __syncthreads();

    // t = relu(acc + ba) -> zs ; load Wb -> ws
#pragma unroll
    for (int i = 0; i < 8; i++) {
        float t[8];
        UNPACK2(t[0], t[1], acc[i][0]);
        UNPACK2(t[2], t[3], acc[i][1]);
        UNPACK2(t[4], t[5], acc[i][2]);
        UNPACK2(t[6], t[7], acc[i][3]);
#pragma unroll
        for (int j = 0; j < 8; j++) t[j] = fmaxf(t[j] + bi[j], 0.f);
        *(float4*)&zs[(ty * 8 + i) * 132 + tx * 8] = *(float4*)&t[0];
        *(float4*)&zs[(ty * 8 + i) * 132 + tx * 8 + 4] = *(float4*)&t[4];
    }
    const float4* wb4 = (const float4*)Wb;
    for (int i = tid; i < 128 * 32; i += 256)
        *(float4*)&ws[(i >> 5) * 128 + (i & 31) * 4] = wb4[i];
    __syncthreads();

#pragma unroll
    for (int i = 0; i < 8; i++)
#pragma unroll
        for (int j = 0; j < 4; j++) acc[i][j] = 0ull;

    // Stage 2: t @ Wb
#pragma unroll 2
    for (int k = 0; k < 128; k++) {
        float4 bA = *(const float4*)&ws[k * 128 + tx * 8];
        float4 bB = *(const float4*)&ws[k * 128 + tx * 8 + 4];
        unsigned long long b0, b1, b2, b3;
        PACK2(b0, bA.x, bA.y); PACK2(b1, bA.z, bA.w);
        PACK2(b2, bB.x, bB.y); PACK2(b3, bB.z, bB.w);
#pragma unroll
        for (int i = 0; i < 8; i++) {
            float a = zs[(ty * 8 + i) * 132 + k];
            unsigned long long a2; PACK2(a2, a, a);
            FMA2(acc[i][0], a2, b0); FMA2(acc[i][1], a2, b1);
            FMA2(acc[i][2], a2, b2); FMA2(acc[i][3], a2, b3);
        }
    }
    *(float4*)&bi[0] = *(const float4*)&bb[tx * 8];
    *(float4*)&bi[4] = *(const float4*)&bb[tx * 8 + 4];

    // h_out = relu(acc + bb) -> g_h
#pragma unroll
    for (int i = 0; i < 8; i++) {
        int gr = row0 + ty * 8 + i;
        if (gr < N_NODES) {
            float t[8];
            UNPACK2(t[0], t[1], acc[i][0]);
            UNPACK2(t[2], t[3], acc[i][1]);
            UNPACK2(t[4], t[5], acc[i][2]);
            UNPACK2(t[6], t[7], acc[i][3]);
#pragma unroll
            for (int j = 0; j < 8; j++) t[j] = fmaxf(t[j] + bi[j], 0.f);
            float* o = g_h + (size_t)gr * 128 + tx * 8;
            *(float4*)&o[0] = *(float4*)&t[0];
            *(float4*)&o[4] = *(float4*)&t[4];
        }
    }
}

// ---------------------------------------------------------------------------
// Head: out = relu(h @ W1 + b1) @ W2 + b2    (128 -> 64 -> 2)
// ---------------------------------------------------------------------------
#define HEAD_SMEM (size_t)((64 * 132 + 128 * 64 + 64 * 68) * sizeof(float))

__global__ __launch_bounds__(256) void head_kernel(
    const float* __restrict__ W1, const float* __restrict__ b1,
    const float* __restrict__ W2, const float* __restrict__ b2,
    float* __restrict__ out) {
    extern __shared__ float sm[];
    float* hs = sm;              // 64 x 132
    float* w1 = sm + 64 * 132;   // 128 x 64
    float* hid = w1 + 128 * 64;  // 64 x 68

    const int tid = threadIdx.x;
    const int tx = tid & 15, ty = tid >> 4;
    const int row0 = blockIdx.x * 64;

    const float4* h4 = (const float4*)g_h;
    for (int i = tid; i < 64 * 32; i += 256) {
        int r = i >> 5, c = i & 31;
        int gr = row0 + r;
        float4 v = make_float4(0.f, 0.f, 0.f, 0.f);
        if (gr < N_NODES) v = h4[(size_t)gr * 32 + c];
        *(float4*)&hs[r * 132 + c * 4] = v;
    }
    const float4* w14 = (const float4*)W1;
    for (int i = tid; i < 128 * 16; i += 256)
        *(float4*)&w1[(i >> 4) * 64 + (i & 15) * 4] = w14[i];
    __syncthreads();

    float acc[4][4];
#pragma unroll
    for (int i = 0; i < 4; i++)
#pragma unroll
        for (int j = 0; j < 4; j++) acc[i][j] = 0.f;

#pragma unroll 4
    for (int k = 0; k < 128; k++) {
        float b[4];
        *(float4*)&b[0] = *(const float4*)&w1[k * 64 + tx * 4];
#pragma unroll
        for (int i = 0; i < 4; i++) {
            float a = hs[(ty * 4 + i) * 132 + k];
#pragma unroll
            for (int j = 0; j < 4; j++) acc[i][j] = fmaf(a, b[j], acc[i][j]);
        }
    }
    float bi[4];
    *(float4*)&bi[0] = *(const float4*)&b1[tx * 4];
#pragma unroll
    for (int i = 0; i < 4; i++) {
        float t[4];
#pragma unroll
        for (int j = 0; j < 4; j++) t[j] = fmaxf(acc[i][j] + bi[j], 0.f);
        *(float4*)&hid[(ty * 4 + i) * 68 + tx * 4] = *(float4*)&t[0];
    }
    __syncthreads();

    if (tid < 128) {
        int r = tid >> 1, c = tid & 1;
        int gr = row0 + r;
        if (gr < N_NODES) {
            float s = __ldg(&b2[c]);
#pragma unroll 8
            for (int k = 0; k < 64; k++)
                s = fmaf(hid[r * 68 + k], __ldg(&W2[k * 2 + c]), s);
            out[(size_t)gr * 2 + c] = s;
        }
    }
}

// ---------------------------------------------------------------------------
extern "C" void kernel_launch(void* const* d_in, const int* in_sizes, int n_in,
                              void* d_out, int out_size) {
    const float* x   = (const float*)d_in[0];
    const void*  ei  = d_in[1];
    const float* eps = (const float*)d_in[2];
    const float* Wa  = (const float*)d_in[3];
    const float* ba  = (const float*)d_in[4];
    const float* Wb  = (const float*)d_in[5];
    const float* bb  = (const float*)d_in[6];
    const float* W1  = (const float*)d_in[7];
    const float* b1  = (const float*)d_in[8];
    const float* W2  = (const float*)d_in[9];
    const float* b2  = (const float*)d_in[10];
    float* out = (float*)d_out;

    cudaFuncSetAttribute(mlp_kernel, cudaFuncAttributeMaxDynamicSharedMemorySize,
                         (int)MLP_SMEM);
    cudaFuncSetAttribute(head_kernel, cudaFuncAttributeMaxDynamicSharedMemorySize,
                         (int)HEAD_SMEM);

    // One-time per launch: dtype detect + CSR build (edges constant across layers)
    detect_kernel<<<1, 32>>>((const long long*)ei);
    zero_deg_kernel<<<(N_NODES + 255) / 256, 256>>>();
    hist_kernel<<<512, 256>>>(ei);
    scan_kernel<<<1, 1024>>>();
    cursor_kernel<<<(N_NODES + 255) / 256, 256>>>();
    fill_kernel<<<512, 256>>>(ei);

    const int gather_blocks = (N_NODES * 32 + 255) / 256;  // warp per node
    const int mlp_blocks = (N_NODES + 127) / 128;          // 391
    const int head_blocks = (N_NODES + 63) / 64;           // 782

    for (int l = 0; l < 3; l++) {
        gather_kernel<<<gather_blocks, 256>>>(x, l > 0 ? 1 : 0, eps, l);
        mlp_kernel<<<mlp_blocks, 256, MLP_SMEM>>>(
            Wa + (size_t)l * HID * HID, ba + (size_t)l * HID,
            Wb + (size_t)l * HID * HID, bb + (size_t)l * HID);
    }
    head_kernel<<<head_blocks, 256, HEAD_SMEM>>>(W1, b1, W2, b2, out);
}

// round 3
// speedup vs baseline: 1.5735x; 1.4601x over previous
#include <cuda_runtime.h>
#include <cstdint>

#define N_NODES 50000
#define N_EDGES 800000
#define HID 128

// Persistent scratch (allocation-free rule: __device__ globals)
__device__ float g_agg[(size_t)N_NODES * HID];   // holds z = (1+eps)h + agg
__device__ float g_h[(size_t)N_NODES * HID];
__device__ int   g_deg[N_NODES];
__device__ int   g_off[N_NODES];
__device__ int   g_cursor[N_NODES];
__device__ int   g_csr[N_EDGES];
__device__ int   g_total;
__device__ int   g_is64;

// f32x2 packed-FMA helpers (sm_100+; ptxas never emits these from C++)
#define FMA2(d, a, b) asm("fma.rn.f32x2 %0,%1,%2,%0;" : "+l"(d) : "l"(a), "l"(b))
#define PACK2(d, x, y) asm("mov.b64 %0,{%1,%2};" : "=l"(d) : "f"(x), "f"(y))
#define UNPACK2(x, y, d) asm("mov.b64 {%0,%1},%2;" : "=f"(x), "=f"(y) : "l"(d))

__device__ __forceinline__ void cp_async16(uint32_t saddr, const void* gptr) {
    asm volatile("cp.async.cg.shared.global [%0], [%1], 16;" ::"r"(saddr), "l"(gptr));
}
#define CP_COMMIT() asm volatile("cp.async.commit_group;")
#define CP_WAIT0()  asm volatile("cp.async.wait_group 0;")

// ---------------------------------------------------------------------------
__global__ void detect_kernel(const long long* __restrict__ ei) {
    if (threadIdx.x == 0 && blockIdx.x == 0) {
        int ok = 1;
        for (int i = 0; i < 64; i++) {
            long long v = ei[i];
            if (v < 0 || v >= N_NODES) { ok = 0; break; }
        }
        g_is64 = ok;
    }
}

// ---------------------------------------------------------------------------
// CSR build (no scan): zero -> histogram -> warp-aggregated base alloc -> fill
// ---------------------------------------------------------------------------
__global__ void zero_deg_kernel() {
    int i = blockIdx.x * blockDim.x + threadIdx.x;
    if (i < N_NODES) g_deg[i] = 0;
    if (i == 0) g_total = 0;
}

__global__ void hist_kernel(const void* __restrict__ ei) {
    const int is64 = g_is64;
    const long long* e64 = (const long long*)ei;
    const int* e32 = (const int*)ei;
    size_t i = (size_t)blockIdx.x * blockDim.x + threadIdx.x;
    const size_t stride = (size_t)gridDim.x * blockDim.x;
    for (size_t e = i; e < (size_t)N_EDGES; e += stride) {
        int dst = is64 ? (int)e64[N_EDGES + e] : e32[N_EDGES + e];
        atomicAdd(&g_deg[dst], 1);
    }
}

// Segment bases need only be disjoint, not ordered: warp shfl-scan + one
// atomicAdd per warp on a global cursor.
__global__ void alloc_kernel() {
    int i = blockIdx.x * blockDim.x + threadIdx.x;
    int lane = threadIdx.x & 31;
    int valid = (i < N_NODES);
    int d = valid ? g_deg[i] : 0;
    int inc = d;
#pragma unroll
    for (int o = 1; o < 32; o <<= 1) {
        int n = __shfl_up_sync(0xffffffffu, inc, o);
        if (lane >= o) inc += n;
    }
    int wsum = __shfl_sync(0xffffffffu, inc, 31);
    int base = 0;
    if (lane == 31) base = atomicAdd(&g_total, wsum);
    base = __shfl_sync(0xffffffffu, base, 31);
    if (valid) {
        int b = base + inc - d;
        g_off[i] = b;
        g_cursor[i] = b;
    }
}

__global__ void fill_kernel(const void* __restrict__ ei) {
    const int is64 = g_is64;
    const long long* e64 = (const long long*)ei;
    const int* e32 = (const int*)ei;
    size_t i = (size_t)blockIdx.x * blockDim.x + threadIdx.x;
    const size_t stride = (size_t)gridDim.x * blockDim.x;
    for (size_t e = i; e < (size_t)N_EDGES; e += stride) {
        int src, dst;
        if (is64) { src = (int)e64[e]; dst = (int)e64[N_EDGES + e]; }
        else      { src = e32[e];      dst = e32[N_EDGES + e]; }
        int pos = atomicAdd(&g_cursor[dst], 1);
        g_csr[pos] = src;
    }
}

// ---------------------------------------------------------------------------
// Gather (atomic-free): one warp per node.
//   z[node] = (1+eps[l]) * h[node] + sum_{s in N(node)} h[s]   -> g_agg
// ---------------------------------------------------------------------------
__global__ __launch_bounds__(256) void gather_kernel(
    const float* __restrict__ x, int use_gh,
    const float* __restrict__ eps, int l) {
    const float* h = use_gh ? g_h : x;
    const int node = (int)(((size_t)blockIdx.x * blockDim.x + threadIdx.x) >> 5);
    const int lane = threadIdx.x & 31;
    if (node >= N_NODES) return;
    const int s0 = g_off[node];
    const int s1 = s0 + g_deg[node];
    const float4* h4 = (const float4*)h;

    float4 a0 = make_float4(0.f, 0.f, 0.f, 0.f);
    float4 a1 = make_float4(0.f, 0.f, 0.f, 0.f);
    float4 a2 = make_float4(0.f, 0.f, 0.f, 0.f);
    float4 a3 = make_float4(0.f, 0.f, 0.f, 0.f);
    int i = s0;
    for (; i + 3 < s1; i += 4) {
        int sa = __ldg(&g_csr[i]);
        int sb = __ldg(&g_csr[i + 1]);
        int sc = __ldg(&g_csr[i + 2]);
        int sd = __ldg(&g_csr[i + 3]);
        float4 va = __ldg(&h4[(size_t)sa * 32 + lane]);
        float4 vb = __ldg(&h4[(size_t)sb * 32 + lane]);
        float4 vc = __ldg(&h4[(size_t)sc * 32 + lane]);
        float4 vd = __ldg(&h4[(size_t)sd * 32 + lane]);
        a0.x += va.x; a0.y += va.y; a0.z += va.z; a0.w += va.w;
        a1.x += vb.x; a1.y += vb.y; a1.z += vb.z; a1.w += vb.w;
        a2.x += vc.x; a2.y += vc.y; a2.z += vc.z; a2.w += vc.w;
        a3.x += vd.x; a3.y += vd.y; a3.z += vd.z; a3.w += vd.w;
    }
    for (; i < s1; i++) {
        int sa = __ldg(&g_csr[i]);
        float4 va = __ldg(&h4[(size_t)sa * 32 + lane]);
        a0.x += va.x; a0.y += va.y; a0.z += va.z; a0.w += va.w;
    }
    a0.x += a1.x + a2.x + a3.x;
    a0.y += a1.y + a2.y + a3.y;
    a0.z += a1.z + a2.z + a3.z;
    a0.w += a1.w + a2.w + a3.w;

    const float sc_ = 1.0f + eps[l];
    float4 hv = h4[(size_t)node * 32 + lane];
    a0.x = fmaf(sc_, hv.x, a0.x);
    a0.y = fmaf(sc_, hv.y, a0.y);
    a0.z = fmaf(sc_, hv.z, a0.z);
    a0.w = fmaf(sc_, hv.w, a0.w);
    *(float4*)&g_agg[(size_t)node * 128 + lane * 4] = a0;
}

// ---------------------------------------------------------------------------
// Fused GIN MLP (packed f32x2 FMAs, k-vectorized A loads, cp.async Wb prefetch)
//   t = relu(z @ Wa + ba);  h_out = relu(t @ Wb + bb)  -> g_h
// Block: 128 rows, 256 threads; 8 rows x 8 cols (4 f32x2 pairs) per thread.
// ---------------------------------------------------------------------------
#define ZPAD 136   // row stride (floats): 136*4=544B, 16B-aligned rows
#define MLP_SMEM (size_t)((128 * ZPAD + 2 * 128 * 128) * sizeof(float))  // 196.6KB

__global__ __launch_bounds__(256) void mlp_kernel(
    const float* __restrict__ Wa, const float* __restrict__ ba,
    const float* __restrict__ Wb, const float* __restrict__ bb) {
    extern __shared__ float sm[];
    float* zs  = sm;                         // 128 x 136
    float* wsa = sm + 128 * ZPAD;            // 128 x 128 (Wa)
    float* wsb = wsa + 128 * 128;            // 128 x 128 (Wb, prefetched)

    const int tid = threadIdx.x;
    const int tx = tid & 15, ty = tid >> 4;
    const int row0 = blockIdx.x * 128;

    // Async load z tile + Wa, prefetch Wb
    const float4* z4 = (const float4*)g_agg;
    for (int i = tid; i < 128 * 32; i += 256) {
        int r = i >> 5, c = i & 31;
        int gr = row0 + r;
        uint32_t dst = (uint32_t)__cvta_generic_to_shared(&zs[r * ZPAD + c * 4]);
        if (gr < N_NODES) cp_async16(dst, &z4[(size_t)gr * 32 + c]);
        else *(float4*)&zs[r * ZPAD + c * 4] = make_float4(0.f, 0.f, 0.f, 0.f);
    }
    const float4* wa4 = (const float4*)Wa;
    const float4* wb4 = (const float4*)Wb;
    for (int i = tid; i < 128 * 32; i += 256) {
        uint32_t dst = (uint32_t)__cvta_generic_to_shared(&wsa[(i >> 5) * 128 + (i & 31) * 4]);
        cp_async16(dst, &wa4[i]);
    }
    for (int i = tid; i < 128 * 32; i += 256) {
        uint32_t dst = (uint32_t)__cvta_generic_to_shared(&wsb[(i >> 5) * 128 + (i & 31) * 4]);
        cp_async16(dst, &wb4[i]);
    }
    CP_COMMIT();
    CP_WAIT0();   // all three (z/Wa needed now; Wb rides along, still hidden vs 2-stage gap)
    __syncthreads();

    unsigned long long acc[8][4];
#pragma unroll
    for (int i = 0; i < 8; i++)
#pragma unroll
        for (int j = 0; j < 4; j++) acc[i][j] = 0ull;

    // Stage 1: z @ Wa
#pragma unroll 2
    for (int k4 = 0; k4 < 32; k4++) {
        float4 a4[8];
#pragma unroll
        for (int i = 0; i < 8; i++)
            a4[i] = *(const float4*)&zs[(ty * 8 + i) * ZPAD + k4 * 4];
#pragma unroll
        for (int kk = 0; kk < 4; kk++) {
            const float* wr = &wsa[(k4 * 4 + kk) * 128 + tx * 8];
            float4 bA = *(const float4*)&wr[0];
            float4 bB = *(const float4*)&wr[4];
            unsigned long long b0, b1, b2, b3;
            PACK2(b0, bA.x, bA.y); PACK2(b1, bA.z, bA.w);
            PACK2(b2, bB.x, bB.y); PACK2(b3, bB.z, bB.w);
#pragma unroll
            for (int i = 0; i < 8; i++) {
                float a = (kk == 0) ? a4[i].x : (kk == 1) ? a4[i].y
                        : (kk == 2) ? a4[i].z : a4[i].w;
                unsigned long long a2; PACK2(a2, a, a);
                FMA2(acc[i][0], a2, b0); FMA2(acc[i][1], a2, b1);
                FMA2(acc[i][2], a2, b2); FMA2(acc[i][3], a2, b3);
            }
        }
    }
    float bi[8];
    *(float4*)&bi[0] = *(const float4*)&ba[tx * 8];
    *(float4*)&bi[4] = *(const float4*)&ba[tx * 8 + 4];
    __syncthreads();

    // t = relu(acc + ba) -> zs
#pragma unroll
    for (int i = 0; i < 8; i++) {
        float t[8];
        UNPACK2(t[0], t[1], acc[i][0]);
        UNPACK2(t[2], t[3], acc[i][1]);
        UNPACK2(t[4], t[5], acc[i][2]);
        UNPACK2(t[6], t[7], acc[i][3]);
#pragma unroll
        for (int j = 0; j < 8; j++) t[j] = fmaxf(t[j] + bi[j], 0.f);
        *(float4*)&zs[(ty * 8 + i) * ZPAD + tx * 8] = *(float4*)&t[0];
        *(float4*)&zs[(ty * 8 + i) * ZPAD + tx * 8 + 4] = *(float4*)&t[4];
    }
    __syncthreads();

#pragma unroll
    for (int i = 0; i < 8; i++)
#pragma unroll
        for (int j = 0; j < 4; j++) acc[i][j] = 0ull;

    // Stage 2: t @ Wb (from prefetched wsb)
#pragma unroll 2
    for (int k4 = 0; k4 < 32; k4++) {
        float4 a4[8];
#pragma unroll
        for (int i = 0; i < 8; i++)
            a4[i] = *(const float4*)&zs[(ty * 8 + i) * ZPAD + k4 * 4];
#pragma unroll
        for (int kk = 0; kk < 4; kk++) {
            const float* wr = &wsb[(k4 * 4 + kk) * 128 + tx * 8];
            float4 bA = *(const float4*)&wr[0];
            float4 bB = *(const float4*)&wr[4];
            unsigned long long b0, b1, b2, b3;
            PACK2(b0, bA.x, bA.y); PACK2(b1, bA.z, bA.w);
            PACK2(b2, bB.x, bB.y); PACK2(b3, bB.z, bB.w);
#pragma unroll
            for (int i = 0; i < 8; i++) {
                float a = (kk == 0) ? a4[i].x : (kk == 1) ? a4[i].y
                        : (kk == 2) ? a4[i].z : a4[i].w;
                unsigned long long a2; PACK2(a2, a, a);
                FMA2(acc[i][0], a2, b0); FMA2(acc[i][1], a2, b1);
                FMA2(acc[i][2], a2, b2); FMA2(acc[i][3], a2, b3);
            }
        }
    }
    *(float4*)&bi[0] = *(const float4*)&bb[tx * 8];
    *(float4*)&bi[4] = *(const float4*)&bb[tx * 8 + 4];

    // h_out = relu(acc + bb) -> g_h
#pragma unroll
    for (int i = 0; i < 8; i++) {
        int gr = row0 + ty * 8 + i;
        if (gr < N_NODES) {
            float t[8];
            UNPACK2(t[0], t[1], acc[i][0]);
            UNPACK2(t[2], t[3], acc[i][1]);
            UNPACK2(t[4], t[5], acc[i][2]);
            UNPACK2(t[6], t[7], acc[i][3]);
#pragma unroll
            for (int j = 0; j < 8; j++) t[j] = fmaxf(t[j] + bi[j], 0.f);
            float* o = g_h + (size_t)gr * 128 + tx * 8;
            *(float4*)&o[0] = *(float4*)&t[0];
            *(float4*)&o[4] = *(float4*)&t[4];
        }
    }
}

// ---------------------------------------------------------------------------
// Head: out = relu(h @ W1 + b1) @ W2 + b2    (128 -> 64 -> 2), f32x2 stage 1
// ---------------------------------------------------------------------------
#define HPAD 136
#define HEAD_SMEM (size_t)((64 * HPAD + 128 * 64 + 64 * 68) * sizeof(float))

__global__ __launch_bounds__(256) void head_kernel(
    const float* __restrict__ W1, const float* __restrict__ b1,
    const float* __restrict__ W2, const float* __restrict__ b2,
    float* __restrict__ out) {
    extern __shared__ float sm[];
    float* hs = sm;               // 64 x 136
    float* w1 = sm + 64 * HPAD;   // 128 x 64
    float* hid = w1 + 128 * 64;   // 64 x 68

    const int tid = threadIdx.x;
    const int tx = tid & 15, ty = tid >> 4;
    const int row0 = blockIdx.x * 64;

    const float4* h4 = (const float4*)g_h;
    for (int i = tid; i < 64 * 32; i += 256) {
        int r = i >> 5, c = i & 31;
        int gr = row0 + r;
        float4 v = make_float4(0.f, 0.f, 0.f, 0.f);
        if (gr < N_NODES) v = h4[(size_t)gr * 32 + c];
        *(float4*)&hs[r * HPAD + c * 4] = v;
    }
    const float4* w14 = (const float4*)W1;
    for (int i = tid; i < 128 * 16; i += 256)
        *(float4*)&w1[(i >> 4) * 64 + (i & 15) * 4] = w14[i];
    __syncthreads();

    unsigned long long acc[4][2];
#pragma unroll
    for (int i = 0; i < 4; i++) { acc[i][0] = 0ull; acc[i][1] = 0ull; }

#pragma unroll 2
    for (int k4 = 0; k4 < 32; k4++) {
        float4 a4[4];
#pragma unroll
        for (int i = 0; i < 4; i++)
            a4[i] = *(const float4*)&hs[(ty * 4 + i) * HPAD + k4 * 4];
#pragma unroll
        for (int kk = 0; kk < 4; kk++) {
            float4 bA = *(const float4*)&w1[(k4 * 4 + kk) * 64 + tx * 4];
            unsigned long long b0, b1;
            PACK2(b0, bA.x, bA.y); PACK2(b1, bA.z, bA.w);
#pragma unroll
            for (int i = 0; i < 4; i++) {
                float a = (kk == 0) ? a4[i].x : (kk == 1) ? a4[i].y
                        : (kk == 2) ? a4[i].z : a4[i].w;
                unsigned long long a2; PACK2(a2, a, a);
                FMA2(acc[i][0], a2, b0); FMA2(acc[i][1], a2, b1);
            }
        }
    }
    float bi[4];
    *(float4*)&bi[0] = *(const float4*)&b1[tx * 4];
#pragma unroll
    for (int i = 0; i < 4; i++) {
        float t[4];
        UNPACK2(t[0], t[1], acc[i][0]);
        UNPACK2(t[2], t[3], acc[i][1]);
#pragma unroll
        for (int j = 0; j < 4; j++) t[j] = fmaxf(t[j] + bi[j], 0.f);
        *(float4*)&hid[(ty * 4 + i) * 68 + tx * 4] = *(float4*)&t[0];
    }
    __syncthreads();

    if (tid < 128) {
        int r = tid >> 1, c = tid & 1;
        int gr = row0 + r;
        if (gr < N_NODES) {
            float s = __ldg(&b2[c]);
#pragma unroll 8
            for (int k = 0; k < 64; k++)
                s = fmaf(hid[r * 68 + k], __ldg(&W2[k * 2 + c]), s);
            out[(size_t)gr * 2 + c] = s;
        }
    }
}

// ---------------------------------------------------------------------------
extern "C" void kernel_launch(void* const* d_in, const int* in_sizes, int n_in,
                              void* d_out, int out_size) {
    const float* x   = (const float*)d_in[0];
    const void*  ei  = d_in[1];
    const float* eps = (const float*)d_in[2];
    const float* Wa  = (const float*)d_in[3];
    const float* ba  = (const float*)d_in[4];
    const float* Wb  = (const float*)d_in[5];
    const float* bb  = (const float*)d_in[6];
    const float* W1  = (const float*)d_in[7];
    const float* b1  = (const float*)d_in[8];
    const float* W2  = (const float*)d_in[9];
    const float* b2  = (const float*)d_in[10];
    float* out = (float*)d_out;

    cudaFuncSetAttribute(mlp_kernel, cudaFuncAttributeMaxDynamicSharedMemorySize,
                         (int)MLP_SMEM);
    cudaFuncSetAttribute(head_kernel, cudaFuncAttributeMaxDynamicSharedMemorySize,
                         (int)HEAD_SMEM);

    // Per-launch CSR build (edges constant across layers); no scan needed.
    detect_kernel<<<1, 32>>>((const long long*)ei);
    zero_deg_kernel<<<(N_NODES + 255) / 256, 256>>>();
    hist_kernel<<<512, 256>>>(ei);
    alloc_kernel<<<(N_NODES + 255) / 256, 256>>>();
    fill_kernel<<<512, 256>>>(ei);

    const int gather_blocks = (N_NODES * 32 + 255) / 256;  // warp per node
    const int mlp_blocks = (N_NODES + 127) / 128;          // 391
    const int head_blocks = (N_NODES + 63) / 64;           // 782

    for (int l = 0; l < 3; l++) {
        gather_kernel<<<gather_blocks, 256>>>(x, l > 0 ? 1 : 0, eps, l);
        mlp_kernel<<<mlp_blocks, 256, MLP_SMEM>>>(
            Wa + (size_t)l * HID * HID, ba + (size_t)l * HID,
            Wb + (size_t)l * HID * HID, bb + (size_t)l * HID);
    }
    head_kernel<<<head_blocks, 256, HEAD_SMEM>>>(W1, b1, W2, b2, out);
}